// round 7
// baseline (speedup 1.0000x reference)
#include <cuda_runtime.h>
#include <cuda_fp16.h>
#include <math.h>

#define NN 100000
#define NE 1600000
#define IN_DIM 128
#define HID 64
#define OUTD 40
#define NB ((NN + 255) / 256)   // 391 scan blocks

// Scratch — __device__ globals (no allocation APIs allowed).
__device__ __half2 g_Ah[NN * 32];    // GEMM output h in fp16 (64 dims = 32 half2)
__device__ float   g_B[NN * 64];     // conv output / GEMM input (fp32)
__device__ int     g_deg[NN];
__device__ float   g_dinv[NN];
__device__ int     g_off[NN];        // CSR row offsets (exclusive)
__device__ int     g_cursor[NN];
__device__ int     g_bsum[512];
__device__ int2    g_csr[NE];        // (src, norm as int bits)
__device__ int     g_is64;

// ---------------- zero deg + edge dtype detection (fused) ----------------
__global__ void zero_detect_kernel(const int* __restrict__ ei32) {
    int i = blockIdx.x * blockDim.x + threadIdx.x;
    if (i < NN) g_deg[i] = 0;
    if (blockIdx.x == 0 && threadIdx.x < 32) {
        int t = threadIdx.x;
        int zeros = 0;
        for (int k = t; k < 2048; k += 32)
            if (ei32[2 * k + 1] == 0) zeros++;
#pragma unroll
        for (int o = 16; o; o >>= 1) zeros += __shfl_xor_sync(0xffffffffu, zeros, o);
        if (t == 0) g_is64 = (zeros > 1536) ? 1 : 0;
    }
}

__device__ __forceinline__ void load_edge(const void* ei, int e, int& s, int& d) {
    if (g_is64) {
        const long long* p = (const long long*)ei;
        s = (int)p[e];
        d = (int)p[(size_t)NE + e];
    } else {
        const int* p = (const int*)ei;
        s = p[e];
        d = p[NE + e];
    }
}

// ---------------- Degree count ----------------
__global__ void deg_kernel(const void* __restrict__ ei) {
    int e = blockIdx.x * blockDim.x + threadIdx.x;
    if (e >= NE) return;
    int s, d;
    load_edge(ei, e, s, d);
    if ((unsigned)d < NN && (unsigned)s < NN) atomicAdd(&g_deg[d], 1);
}

// Exclusive scan of g_deg -> g_off (3 phases); scan1 also emits dinv.
__global__ void scan1() {
    __shared__ int sh[256];
    int t = threadIdx.x, i = blockIdx.x * 256 + t;
    int v = (i < NN) ? g_deg[i] : 0;
    if (i < NN) g_dinv[i] = rsqrtf((float)v + 1.0f);  // +1 = self-loop
    sh[t] = v;
    __syncthreads();
    for (int off = 1; off < 256; off <<= 1) {
        int x = (t >= off) ? sh[t - off] : 0;
        __syncthreads();
        sh[t] += x;
        __syncthreads();
    }
    if (i < NN) g_off[i] = sh[t] - v;
    if (t == 255) g_bsum[blockIdx.x] = sh[255];
}

__global__ void scan2() {
    __shared__ int sh[512];
    int t = threadIdx.x;
    int v = (t < NB) ? g_bsum[t] : 0;
    sh[t] = v;
    __syncthreads();
    for (int off = 1; off < 512; off <<= 1) {
        int x = (t >= off) ? sh[t - off] : 0;
        __syncthreads();
        sh[t] += x;
        __syncthreads();
    }
    if (t < NB) g_bsum[t] = sh[t] - v;
}

__global__ void scan3() {
    int i = blockIdx.x * blockDim.x + threadIdx.x;
    if (i < NN) {
        int o = g_off[i] + g_bsum[i >> 8];
        g_off[i] = o;
        g_cursor[i] = o;
    }
}

__global__ void fill_kernel(const void* __restrict__ ei) {
    int e = blockIdx.x * blockDim.x + threadIdx.x;
    if (e >= NE) return;
    int s, d;
    load_edge(ei, e, s, d);
    if ((unsigned)s >= NN || (unsigned)d >= NN) return;
    int pos = atomicAdd(&g_cursor[d], 1);
    g_csr[pos] = make_int2(s, __float_as_int(g_dinv[s] * g_dinv[d]));
}

// ---------------- GEMM: g_Ah[M,64](fp16) = X[M,K](fp32) @ W[K,64] ----------------

template <int K, bool FROMB>
__global__ __launch_bounds__(256) void gemm64(
    const float* __restrict__ Xin, const float* __restrict__ W, int M)
{
    constexpr int PAD = (K == 128) ? 0 : 4;   // keeps static smem <= 48KB at K=128
    const float* __restrict__ X = FROMB ? (const float*)g_B : Xin;
    __shared__ float Ws[K * 64];
    __shared__ float Xs[32 * (K + PAD)];
    const int tid = threadIdx.x;

    for (int i = tid; i < K * 64; i += 256) Ws[i] = W[i];
    const int r0 = blockIdx.x * 32;
    for (int i = tid; i < 32 * K; i += 256) {
        int r = i / K, k = i - r * K;
        int gr = r0 + r;
        Xs[r * (K + PAD) + k] = (gr < M) ? X[(size_t)gr * K + k] : 0.f;
    }
    __syncthreads();

    const int cx = tid & 15;
    const int ry = tid >> 4;
    const float4* x0p = (const float4*)&Xs[(2 * ry) * (K + PAD)];
    const float4* x1p = (const float4*)&Xs[(2 * ry + 1) * (K + PAD)];

    float4 a0 = make_float4(0.f, 0.f, 0.f, 0.f);
    float4 a1 = make_float4(0.f, 0.f, 0.f, 0.f);
#pragma unroll 8
    for (int kk = 0; kk < K / 4; kk++) {
        float4 xa = x0p[kk];
        float4 xb = x1p[kk];
        float4 w0 = *(const float4*)&Ws[(4 * kk + 0) * 64 + cx * 4];
        float4 w1 = *(const float4*)&Ws[(4 * kk + 1) * 64 + cx * 4];
        float4 w2 = *(const float4*)&Ws[(4 * kk + 2) * 64 + cx * 4];
        float4 w3 = *(const float4*)&Ws[(4 * kk + 3) * 64 + cx * 4];
        a0.x = fmaf(xa.x, w0.x, a0.x); a0.y = fmaf(xa.x, w0.y, a0.y);
        a0.z = fmaf(xa.x, w0.z, a0.z); a0.w = fmaf(xa.x, w0.w, a0.w);
        a1.x = fmaf(xb.x, w0.x, a1.x); a1.y = fmaf(xb.x, w0.y, a1.y);
        a1.z = fmaf(xb.x, w0.z, a1.z); a1.w = fmaf(xb.x, w0.w, a1.w);
        a0.x = fmaf(xa.y, w1.x, a0.x); a0.y = fmaf(xa.y, w1.y, a0.y);
        a0.z = fmaf(xa.y, w1.z, a0.z); a0.w = fmaf(xa.y, w1.w, a0.w);
        a1.x = fmaf(xb.y, w1.x, a1.x); a1.y = fmaf(xb.y, w1.y, a1.y);
        a1.z = fmaf(xb.y, w1.z, a1.z); a1.w = fmaf(xb.y, w1.w, a1.w);
        a0.x = fmaf(xa.z, w2.x, a0.x); a0.y = fmaf(xa.z, w2.y, a0.y);
        a0.z = fmaf(xa.z, w2.z, a0.z); a0.w = fmaf(xa.z, w2.w, a0.w);
        a1.x = fmaf(xb.z, w2.x, a1.x); a1.y = fmaf(xb.z, w2.y, a1.y);
        a1.z = fmaf(xb.z, w2.z, a1.z); a1.w = fmaf(xb.z, w2.w, a1.w);
        a0.x = fmaf(xa.w, w3.x, a0.x); a0.y = fmaf(xa.w, w3.y, a0.y);
        a0.z = fmaf(xa.w, w3.z, a0.z); a0.w = fmaf(xa.w, w3.w, a0.w);
        a1.x = fmaf(xb.w, w3.x, a1.x); a1.y = fmaf(xb.w, w3.y, a1.y);
        a1.z = fmaf(xb.w, w3.z, a1.z); a1.w = fmaf(xb.w, w3.w, a1.w);
    }
    const int r = r0 + 2 * ry;
    if (r < M) {
        g_Ah[(size_t)r * 32 + cx * 2]     = __floats2half2_rn(a0.x, a0.y);
        g_Ah[(size_t)r * 32 + cx * 2 + 1] = __floats2half2_rn(a0.z, a0.w);
    }
    if (r + 1 < M) {
        g_Ah[(size_t)(r + 1) * 32 + cx * 2]     = __floats2half2_rn(a1.x, a1.y);
        g_Ah[(size_t)(r + 1) * 32 + cx * 2 + 1] = __floats2half2_rn(a1.z, a1.w);
    }
}

// ---------------- Gather (+ optional fused head) ----------------
// Warp per node; lane owns dims {2*lane, 2*lane+1}. Edge meta loaded
// coalesced (lane -> edge) and distributed via shuffles; row loads in
// zero-padded groups of 8 -> MLP 8 everywhere, no serial tail.

template <bool HEAD>
__global__ __launch_bounds__(256) void gather_kernel(
    const float* __restrict__ b, int relu,
    const float* __restrict__ Wl, const float* __restrict__ bl,
    float* __restrict__ out)
{
    __shared__ float Wls[HEAD ? 64 * OUTD : 1];
    __shared__ float bls[HEAD ? OUTD : 1];
    __shared__ float rowS[HEAD ? 8 : 1][64];

    const int tid = threadIdx.x;
    if (HEAD) {
        for (int i = tid; i < 64 * OUTD; i += 256) Wls[i] = Wl[i];
        if (tid < OUTD) bls[tid] = bl[tid];
        __syncthreads();
    }

    int node = (blockIdx.x * blockDim.x + tid) >> 5;
    int lane = tid & 31;
    if (node >= NN) return;

    int j0 = g_off[node];
    int end = j0 + g_deg[node];

    float a0 = 0.f, a1 = 0.f;

    for (int base = j0; base < end; base += 32) {
        int rem = end - base;
        int2 meta = make_int2(0, 0);           // norm bits 0 => 0.0f padding
        if (lane < rem) meta = __ldg(&g_csr[base + lane]);
        int cnt = rem < 32 ? rem : 32;
        int nGrp = (cnt + 7) >> 3;
        for (int g = 0; g < nGrp; g++) {
            int i = g * 8;
            float2 v[8];
            float nrm[8];
#pragma unroll
            for (int u = 0; u < 8; u++) {
                int s = __shfl_sync(0xffffffffu, meta.x, i + u);
                nrm[u] = __int_as_float(__shfl_sync(0xffffffffu, meta.y, i + u));
                v[u] = __half22float2(g_Ah[(size_t)s * 32 + lane]);
            }
#pragma unroll
            for (int u = 0; u < 8; u++) {
                a0 = fmaf(v[u].x, nrm[u], a0);
                a1 = fmaf(v[u].y, nrm[u], a1);
            }
        }
    }

    float di = g_dinv[node];
    float self = di * di;
    float2 vs = __half22float2(g_Ah[(size_t)node * 32 + lane]);
    a0 = fmaf(vs.x, self, a0) + b[2 * lane];
    a1 = fmaf(vs.y, self, a1) + b[2 * lane + 1];

    if (!HEAD) {
        if (relu) { a0 = fmaxf(a0, 0.f); a1 = fmaxf(a1, 0.f); }
        *(float2*)&g_B[(size_t)node * 64 + 2 * lane] = make_float2(a0, a1);
        return;
    }

    // Fused head: logits = emb @ Wl + bl; out = log_softmax(logits).
    const int w = tid >> 5;
    rowS[w][2 * lane] = a0;
    rowS[w][2 * lane + 1] = a1;
    __syncwarp();

    float acc0 = bls[lane];
    float acc1 = (lane < 8) ? bls[32 + lane] : 0.f;
#pragma unroll
    for (int k = 0; k < 64; k++) {
        float ek = rowS[w][k];
        acc0 = fmaf(ek, Wls[k * OUTD + lane], acc0);
        if (lane < 8) acc1 = fmaf(ek, Wls[k * OUTD + 32 + lane], acc1);
    }

    float m = acc0;
    if (lane < 8) m = fmaxf(m, acc1);
#pragma unroll
    for (int off = 16; off; off >>= 1) m = fmaxf(m, __shfl_xor_sync(0xffffffffu, m, off));
    float sum = expf(acc0 - m) + ((lane < 8) ? expf(acc1 - m) : 0.f);
#pragma unroll
    for (int off = 16; off; off >>= 1) sum += __shfl_xor_sync(0xffffffffu, sum, off);
    float lse = m + logf(sum);

    out[(size_t)node * OUTD + lane] = acc0 - lse;
    if (lane < 8) out[(size_t)node * OUTD + 32 + lane] = acc1 - lse;
}

// ---------------- Launch ----------------

extern "C" void kernel_launch(void* const* d_in, const int* in_sizes, int n_in,
                              void* d_out, int out_size)
{
    const float* x  = (const float*)d_in[0];
    const void*  ei = d_in[1];
    const float* W1 = (const float*)d_in[2];
    const float* b1 = (const float*)d_in[3];
    const float* W2 = (const float*)d_in[4];
    const float* b2 = (const float*)d_in[5];
    const float* Wl = (const float*)d_in[6];
    const float* bl = (const float*)d_in[7];
    float* out = (float*)d_out;

    const int M = NN;
    const int NBLK = (NN + 255) / 256;
    const int EBLK = (NE + 255) / 256;

    // CSR build (graph shared by both layers)
    zero_detect_kernel<<<NBLK, 256>>>((const int*)ei);
    deg_kernel<<<EBLK, 256>>>(ei);
    scan1<<<NB, 256>>>();
    scan2<<<1, 512>>>();
    scan3<<<NBLK, 256>>>();
    fill_kernel<<<EBLK, 256>>>(ei);

    // Layer 1
    gemm64<IN_DIM, false><<<(M + 31) / 32, 256>>>(x, W1, M);
    gather_kernel<false><<<(M * 32 + 255) / 256, 256>>>(b1, 1, nullptr, nullptr, nullptr);

    // Layer 2 + fused head
    gemm64<HID, true><<<(M + 31) / 32, 256>>>(nullptr, W2, M);
    gather_kernel<true><<<(M * 32 + 255) / 256, 256>>>(b2, 0, Wl, bl, out);
}

// round 8
// speedup vs baseline: 1.3887x; 1.3887x over previous
#include <cuda_runtime.h>
#include <cuda_fp16.h>
#include <math.h>

#define NN 100000
#define NE 1600000
#define IN_DIM 128
#define HID 64
#define OUTD 40
#define NB ((NN + 255) / 256)   // 391 scan blocks

// Scratch — __device__ globals (no allocation APIs allowed).
__device__ __half2 g_Ah[NN * 32];    // GEMM output h in fp16 (64 dims = 32 half2)
__device__ float   g_B[NN * 64];     // conv output / layer-2 GEMM input (fp32)
__device__ int     g_deg[NN];
__device__ float   g_dinv[NN];
__device__ int     g_off[NN];        // CSR row offsets (exclusive)
__device__ int     g_cursor[NN];
__device__ int     g_bsum[512];
__device__ int2    g_csr[NE];        // (src, norm as int bits)
__device__ int     g_is64;

// ---------------- zero deg + edge dtype detection (fused) ----------------
__global__ void zero_detect_kernel(const int* __restrict__ ei32) {
    int i = blockIdx.x * blockDim.x + threadIdx.x;
    if (i < NN) g_deg[i] = 0;
    if (blockIdx.x == 0 && threadIdx.x < 32) {
        int t = threadIdx.x;
        int zeros = 0;
        for (int k = t; k < 2048; k += 32)
            if (ei32[2 * k + 1] == 0) zeros++;
#pragma unroll
        for (int o = 16; o; o >>= 1) zeros += __shfl_xor_sync(0xffffffffu, zeros, o);
        if (t == 0) g_is64 = (zeros > 1536) ? 1 : 0;
    }
}

__device__ __forceinline__ void load_edge(const void* ei, int e, int& s, int& d) {
    if (g_is64) {
        const long long* p = (const long long*)ei;
        s = (int)p[e];
        d = (int)p[(size_t)NE + e];
    } else {
        const int* p = (const int*)ei;
        s = p[e];
        d = p[NE + e];
    }
}

__global__ void deg_kernel(const void* __restrict__ ei) {
    int e = blockIdx.x * blockDim.x + threadIdx.x;
    if (e >= NE) return;
    int s, d;
    load_edge(ei, e, s, d);
    if ((unsigned)d < NN && (unsigned)s < NN) atomicAdd(&g_deg[d], 1);
}

// Exclusive scan of g_deg -> g_off (3 phases); scan1 also emits dinv.
__global__ void scan1() {
    __shared__ int sh[256];
    int t = threadIdx.x, i = blockIdx.x * 256 + t;
    int v = (i < NN) ? g_deg[i] : 0;
    if (i < NN) g_dinv[i] = rsqrtf((float)v + 1.0f);  // +1 = self-loop
    sh[t] = v;
    __syncthreads();
    for (int off = 1; off < 256; off <<= 1) {
        int x = (t >= off) ? sh[t - off] : 0;
        __syncthreads();
        sh[t] += x;
        __syncthreads();
    }
    if (i < NN) g_off[i] = sh[t] - v;
    if (t == 255) g_bsum[blockIdx.x] = sh[255];
}

__global__ void scan2() {
    __shared__ int sh[512];
    int t = threadIdx.x;
    int v = (t < NB) ? g_bsum[t] : 0;
    sh[t] = v;
    __syncthreads();
    for (int off = 1; off < 512; off <<= 1) {
        int x = (t >= off) ? sh[t - off] : 0;
        __syncthreads();
        sh[t] += x;
        __syncthreads();
    }
    if (t < NB) g_bsum[t] = sh[t] - v;
}

__global__ void scan3() {
    int i = blockIdx.x * blockDim.x + threadIdx.x;
    if (i < NN) {
        int o = g_off[i] + g_bsum[i >> 8];
        g_off[i] = o;
        g_cursor[i] = o;
    }
}

__global__ void fill_kernel(const void* __restrict__ ei) {
    int e = blockIdx.x * blockDim.x + threadIdx.x;
    if (e >= NE) return;
    int s, d;
    load_edge(ei, e, s, d);
    if ((unsigned)s >= NN || (unsigned)d >= NN) return;
    int pos = atomicAdd(&g_cursor[d], 1);
    g_csr[pos] = make_int2(s, __float_as_int(g_dinv[s] * g_dinv[d]));
}

// ---------------- Tensor-core GEMM: g_Ah[M,64](fp16) = X[M,K] @ W[K,64] ----------------
// Block = 128 threads (4 warps); block tile 64 rows x 64 cols, full K in smem.
// mma.sync.m16n8k16 row.col, fp16 inputs, fp32 accum. Warp w owns rows w*16..w*16+15.

template <int K, bool FROMB>
__global__ __launch_bounds__(128) void gemm_tc(
    const float* __restrict__ Xin, const float* __restrict__ W, int M)
{
    constexpr int LDA = K + 8;   // halves; row stride 2*LDA bytes -> conflict-free frags
    const float* __restrict__ X = FROMB ? (const float*)g_B : Xin;

    __shared__ __half As[64 * LDA];   // [row][k]
    __shared__ __half Wt[64 * LDA];   // [n][k]  (B col-major for mma .col)

    const int tid = threadIdx.x;
    const int r0 = blockIdx.x * 64;

    // Stage X (fp32 -> fp16), rows r0..r0+63
    for (int i = tid; i < 64 * K; i += 128) {
        int r = i / K, k = i - r * K;
        int gr = r0 + r;
        As[r * LDA + k] = __float2half((gr < M) ? X[(size_t)gr * K + k] : 0.f);
    }
    // Stage W transposed: Wt[n][k] = W[k][n]
    for (int i = tid; i < 64 * K; i += 128) {
        int k = i / 64, n = i - k * 64;
        Wt[n * LDA + k] = __float2half(W[(size_t)k * 64 + n]);
    }
    __syncthreads();

    const int w = tid >> 5;       // warp 0..3, rows w*16..
    const int T = tid & 31;
    const int qr = T >> 2;        // T/4
    const int qc = T & 3;         // T%4

    float c[8][4];
#pragma unroll
    for (int n = 0; n < 8; n++)
#pragma unroll
        for (int j = 0; j < 4; j++) c[n][j] = 0.f;

    const __half* Abase = &As[(w * 16 + qr) * LDA + qc * 2];

#pragma unroll
    for (int ks = 0; ks < K / 16; ks++) {
        unsigned a0 = *(const unsigned*)(Abase + ks * 16);
        unsigned a1 = *(const unsigned*)(Abase + 8 * LDA + ks * 16);
        unsigned a2 = *(const unsigned*)(Abase + ks * 16 + 8);
        unsigned a3 = *(const unsigned*)(Abase + 8 * LDA + ks * 16 + 8);
#pragma unroll
        for (int n = 0; n < 8; n++) {
            const __half* Bbase = &Wt[(n * 8 + qr) * LDA + qc * 2 + ks * 16];
            unsigned b0 = *(const unsigned*)(Bbase);
            unsigned b1 = *(const unsigned*)(Bbase + 8);
            asm volatile(
                "mma.sync.aligned.m16n8k16.row.col.f32.f16.f16.f32 "
                "{%0,%1,%2,%3}, {%4,%5,%6,%7}, {%8,%9}, {%0,%1,%2,%3};"
                : "+f"(c[n][0]), "+f"(c[n][1]), "+f"(c[n][2]), "+f"(c[n][3])
                : "r"(a0), "r"(a1), "r"(a2), "r"(a3), "r"(b0), "r"(b1));
        }
    }

    // Epilogue: thread holds rows {qr, qr+8} of warp tile, cols n*8 + qc*2 (+1).
    const int row0 = r0 + w * 16 + qr;
#pragma unroll
    for (int n = 0; n < 8; n++) {
        int cidx = n * 4 + qc;   // half2 index (cols n*8+qc*2, +1)
        if (row0 < M)
            g_Ah[(size_t)row0 * 32 + cidx] = __floats2half2_rn(c[n][0], c[n][1]);
        if (row0 + 8 < M)
            g_Ah[(size_t)(row0 + 8) * 32 + cidx] = __floats2half2_rn(c[n][2], c[n][3]);
    }
}

// ---------------- Gather (+ optional fused head) ----------------
// Warp per node; lane owns dims {2*lane, 2*lane+1}. Edge meta loaded
// coalesced and distributed via shuffles; row loads in zero-padded groups of 8.

template <bool HEAD>
__global__ __launch_bounds__(256) void gather_kernel(
    const float* __restrict__ b, int relu,
    const float* __restrict__ Wl, const float* __restrict__ bl,
    float* __restrict__ out)
{
    __shared__ float Wls[HEAD ? 64 * OUTD : 1];
    __shared__ float bls[HEAD ? OUTD : 1];
    __shared__ float rowS[HEAD ? 8 : 1][64];

    const int tid = threadIdx.x;
    if (HEAD) {
        for (int i = tid; i < 64 * OUTD; i += 256) Wls[i] = Wl[i];
        if (tid < OUTD) bls[tid] = bl[tid];
        __syncthreads();
    }

    int node = (blockIdx.x * blockDim.x + tid) >> 5;
    int lane = tid & 31;
    if (node >= NN) return;

    int j0 = g_off[node];
    int end = j0 + g_deg[node];

    float a0 = 0.f, a1 = 0.f;

    for (int base = j0; base < end; base += 32) {
        int rem = end - base;
        int2 meta = make_int2(0, 0);           // norm bits 0 => 0.0f padding
        if (lane < rem) meta = __ldg(&g_csr[base + lane]);
        int cnt = rem < 32 ? rem : 32;
        int nGrp = (cnt + 7) >> 3;
        for (int g = 0; g < nGrp; g++) {
            int i = g * 8;
            float2 v[8];
            float nrm[8];
#pragma unroll
            for (int u = 0; u < 8; u++) {
                int s = __shfl_sync(0xffffffffu, meta.x, i + u);
                nrm[u] = __int_as_float(__shfl_sync(0xffffffffu, meta.y, i + u));
                v[u] = __half22float2(g_Ah[(size_t)s * 32 + lane]);
            }
#pragma unroll
            for (int u = 0; u < 8; u++) {
                a0 = fmaf(v[u].x, nrm[u], a0);
                a1 = fmaf(v[u].y, nrm[u], a1);
            }
        }
    }

    float di = g_dinv[node];
    float self = di * di;
    float2 vs = __half22float2(g_Ah[(size_t)node * 32 + lane]);
    a0 = fmaf(vs.x, self, a0) + b[2 * lane];
    a1 = fmaf(vs.y, self, a1) + b[2 * lane + 1];

    if (!HEAD) {
        if (relu) { a0 = fmaxf(a0, 0.f); a1 = fmaxf(a1, 0.f); }
        *(float2*)&g_B[(size_t)node * 64 + 2 * lane] = make_float2(a0, a1);
        return;
    }

    // Fused head: logits = emb @ Wl + bl; out = log_softmax(logits).
    const int w = tid >> 5;
    rowS[w][2 * lane] = a0;
    rowS[w][2 * lane + 1] = a1;
    __syncwarp();

    float acc0 = bls[lane];
    float acc1 = (lane < 8) ? bls[32 + lane] : 0.f;
#pragma unroll
    for (int k = 0; k < 64; k++) {
        float ek = rowS[w][k];
        acc0 = fmaf(ek, Wls[k * OUTD + lane], acc0);
        if (lane < 8) acc1 = fmaf(ek, Wls[k * OUTD + 32 + lane], acc1);
    }

    float m = acc0;
    if (lane < 8) m = fmaxf(m, acc1);
#pragma unroll
    for (int off = 16; off; off >>= 1) m = fmaxf(m, __shfl_xor_sync(0xffffffffu, m, off));
    float sum = expf(acc0 - m) + ((lane < 8) ? expf(acc1 - m) : 0.f);
#pragma unroll
    for (int off = 16; off; off >>= 1) sum += __shfl_xor_sync(0xffffffffu, sum, off);
    float lse = m + logf(sum);

    out[(size_t)node * OUTD + lane] = acc0 - lse;
    if (lane < 8) out[(size_t)node * OUTD + 32 + lane] = acc1 - lse;
}

// ---------------- Launch ----------------

extern "C" void kernel_launch(void* const* d_in, const int* in_sizes, int n_in,
                              void* d_out, int out_size)
{
    const float* x  = (const float*)d_in[0];
    const void*  ei = d_in[1];
    const float* W1 = (const float*)d_in[2];
    const float* b1 = (const float*)d_in[3];
    const float* W2 = (const float*)d_in[4];
    const float* b2 = (const float*)d_in[5];
    const float* Wl = (const float*)d_in[6];
    const float* bl = (const float*)d_in[7];
    float* out = (float*)d_out;

    const int M = NN;
    const int NBLK = (NN + 255) / 256;
    const int EBLK = (NE + 255) / 256;
    const int GBLK = (M + 63) / 64;

    // CSR build; gemm1 (CSR-independent) placed at launch index 3 so the
    // ncu capture (-s 5 -c 1 => observed index 3) profiles it.
    zero_detect_kernel<<<NBLK, 256>>>((const int*)ei);
    deg_kernel<<<EBLK, 256>>>(ei);
    scan1<<<NB, 256>>>();
    gemm_tc<IN_DIM, false><<<GBLK, 128>>>(x, W1, M);
    scan2<<<1, 512>>>();
    scan3<<<NBLK, 256>>>();
    fill_kernel<<<EBLK, 256>>>(ei);

    // Layer 1 aggregate
    gather_kernel<false><<<(M * 32 + 255) / 256, 256>>>(b1, 1, nullptr, nullptr, nullptr);

    // Layer 2 + fused head
    gemm_tc<HID, true><<<GBLK, 128>>>(nullptr, W2, M);
    gather_kernel<true><<<(M * 32 + 255) / 256, 256>>>(b2, 0, Wl, bl, out);
}

// round 9
// speedup vs baseline: 1.4342x; 1.0327x over previous
#include <cuda_runtime.h>
#include <cuda_fp16.h>
#include <math.h>

#define NN 100000
#define NE 1600000
#define IN_DIM 128
#define HID 64
#define OUTD 40
#define NB ((NN + 255) / 256)   // 391 scan blocks

// Scratch — __device__ globals (no allocation APIs allowed).
__device__ __half2 g_Ah[NN * 32];    // GEMM output h in fp16 (64 dims = 32 half2)
__device__ float   g_B[NN * 64];     // conv output / layer-2 GEMM input (fp32)
__device__ int     g_deg[NN];
__device__ float   g_dinv[NN];
__device__ int     g_off[NN];        // local (per-256-chunk) exclusive offsets; inclusive after fill
__device__ int     g_bsum[512];      // scanned chunk sums
__device__ int2    g_csr[NE];        // (src, norm as int bits)
__device__ int     g_is64;

// ---------------- zero deg + edge dtype detection (fused) ----------------
__global__ void zero_detect_kernel(const int* __restrict__ ei32) {
    int i = blockIdx.x * blockDim.x + threadIdx.x;
    if (i < NN) g_deg[i] = 0;
    if (blockIdx.x == 0 && threadIdx.x < 32) {
        int t = threadIdx.x;
        int zeros = 0;
        for (int k = t; k < 2048; k += 32)
            if (ei32[2 * k + 1] == 0) zeros++;
#pragma unroll
        for (int o = 16; o; o >>= 1) zeros += __shfl_xor_sync(0xffffffffu, zeros, o);
        if (t == 0) g_is64 = (zeros > 1536) ? 1 : 0;
    }
}

__device__ __forceinline__ void load_edge(const void* ei, int e, int& s, int& d) {
    if (g_is64) {
        const long long* p = (const long long*)ei;
        s = (int)p[e];
        d = (int)p[(size_t)NE + e];
    } else {
        const int* p = (const int*)ei;
        s = p[e];
        d = p[NE + e];
    }
}

__global__ void deg_kernel(const void* __restrict__ ei) {
    int e = blockIdx.x * blockDim.x + threadIdx.x;
    if (e >= NE) return;
    int s, d;
    load_edge(ei, e, s, d);
    if ((unsigned)d < NN && (unsigned)s < NN) atomicAdd(&g_deg[d], 1);
}

// scan1: local exclusive scan of deg within 256-chunks; chunk sums -> g_bsum; also dinv.
__global__ void scan1() {
    __shared__ int sh[256];
    int t = threadIdx.x, i = blockIdx.x * 256 + t;
    int v = (i < NN) ? g_deg[i] : 0;
    if (i < NN) g_dinv[i] = rsqrtf((float)v + 1.0f);  // +1 = self-loop
    sh[t] = v;
    __syncthreads();
    for (int off = 1; off < 256; off <<= 1) {
        int x = (t >= off) ? sh[t - off] : 0;
        __syncthreads();
        sh[t] += x;
        __syncthreads();
    }
    if (i < NN) g_off[i] = sh[t] - v;
    if (t == 255) g_bsum[blockIdx.x] = sh[255];
}

__global__ void scan2() {
    __shared__ int sh[512];
    int t = threadIdx.x;
    int v = (t < NB) ? g_bsum[t] : 0;
    sh[t] = v;
    __syncthreads();
    for (int off = 1; off < 512; off <<= 1) {
        int x = (t >= off) ? sh[t - off] : 0;
        __syncthreads();
        sh[t] += x;
        __syncthreads();
    }
    if (t < NB) g_bsum[t] = sh[t] - v;
}

// fill: absolute pos = bsum[chunk] + local off; bump local off (becomes inclusive end).
__global__ void fill_kernel(const void* __restrict__ ei) {
    int e = blockIdx.x * blockDim.x + threadIdx.x;
    if (e >= NE) return;
    int s, d;
    load_edge(ei, e, s, d);
    if ((unsigned)s >= NN || (unsigned)d >= NN) return;
    int pos = g_bsum[d >> 8] + atomicAdd(&g_off[d], 1);
    g_csr[pos] = make_int2(s, __float_as_int(g_dinv[s] * g_dinv[d]));
}

// ---------------- ldmatrix helpers ----------------
__device__ __forceinline__ void ldsm_x4(unsigned& r0, unsigned& r1, unsigned& r2, unsigned& r3,
                                        const void* p) {
    unsigned addr = (unsigned)__cvta_generic_to_shared(p);
    asm volatile("ldmatrix.sync.aligned.m8n8.x4.shared.b16 {%0,%1,%2,%3}, [%4];"
                 : "=r"(r0), "=r"(r1), "=r"(r2), "=r"(r3) : "r"(addr));
}
__device__ __forceinline__ void ldsm_x4t(unsigned& r0, unsigned& r1, unsigned& r2, unsigned& r3,
                                         const void* p) {
    unsigned addr = (unsigned)__cvta_generic_to_shared(p);
    asm volatile("ldmatrix.sync.aligned.m8n8.x4.trans.shared.b16 {%0,%1,%2,%3}, [%4];"
                 : "=r"(r0), "=r"(r1), "=r"(r2), "=r"(r3) : "r"(addr));
}

// ---------------- Tensor-core GEMM: g_Ah[M,64](fp16) = X[M,K] @ W[K,64] ----------------
// 128 threads (4 warps); each block processes 4 row-tiles of 64 rows (W staged once).
// mma.sync.m16n8k16 row.col; A fragments via ldmatrix.x4, B via ldmatrix.x4.trans.

template <int K, bool FROMB>
__global__ __launch_bounds__(128) void gemm_tc(
    const float* __restrict__ Xin, const float* __restrict__ W, int M)
{
    constexpr int LDA = K + 8;       // halves
    constexpr int LDB = 64 + 8;      // halves, W natural [k][n]
    const float* __restrict__ X = FROMB ? (const float*)g_B : Xin;

    __shared__ __half As[64 * LDA];
    __shared__ __half Ws[K * LDB];

    const int tid = threadIdx.x;

    // Stage W [k][n] (float4 -> 2x half2), once per block
    for (int i = tid; i < K * 16; i += 128) {        // K*64/4 float4s
        int k = i >> 4, n4 = (i & 15) * 4;
        float4 wv = *(const float4*)&W[(size_t)k * 64 + n4];
        *(__half2*)&Ws[k * LDB + n4]     = __floats2half2_rn(wv.x, wv.y);
        *(__half2*)&Ws[k * LDB + n4 + 2] = __floats2half2_rn(wv.z, wv.w);
    }

    const int w = tid >> 5;
    const int T = tid & 31;
    const int qr = T >> 2, qc = T & 3;
    const int arow = w * 16 + (T & 15);
    const int acol = ((T >> 4) & 1) * 8;
    const int krow_off = (T & 7) + ((T >> 3) & 1) * 8;
    const int ncol_half = ((T >> 4) & 1) * 8;

    for (int t = 0; t < 4; t++) {
        const int r0 = (blockIdx.x * 4 + t) * 64;
        if (r0 >= M) break;
        __syncthreads();
        // Stage X rows r0..r0+63 (float4 -> 2x half2)
        for (int i = tid; i < 64 * (K / 4); i += 128) {
            int r = i / (K / 4), k4 = (i % (K / 4)) * 4;
            int gr = r0 + r;
            float4 xv = (gr < M) ? *(const float4*)&X[(size_t)gr * K + k4]
                                 : make_float4(0.f, 0.f, 0.f, 0.f);
            *(__half2*)&As[r * LDA + k4]     = __floats2half2_rn(xv.x, xv.y);
            *(__half2*)&As[r * LDA + k4 + 2] = __floats2half2_rn(xv.z, xv.w);
        }
        __syncthreads();

        float c[8][4];
#pragma unroll
        for (int n = 0; n < 8; n++)
#pragma unroll
            for (int j = 0; j < 4; j++) c[n][j] = 0.f;

#pragma unroll
        for (int ks = 0; ks < K / 16; ks++) {
            unsigned a0, a1, a2, a3;
            ldsm_x4(a0, a1, a2, a3, &As[arow * LDA + ks * 16 + acol]);
            unsigned bb[16];
#pragma unroll
            for (int p = 0; p < 4; p++) {
                ldsm_x4t(bb[4 * p], bb[4 * p + 1], bb[4 * p + 2], bb[4 * p + 3],
                         &Ws[(ks * 16 + krow_off) * LDB + p * 16 + ncol_half]);
            }
#pragma unroll
            for (int n = 0; n < 8; n++) {
                asm volatile(
                    "mma.sync.aligned.m16n8k16.row.col.f32.f16.f16.f32 "
                    "{%0,%1,%2,%3}, {%4,%5,%6,%7}, {%8,%9}, {%0,%1,%2,%3};"
                    : "+f"(c[n][0]), "+f"(c[n][1]), "+f"(c[n][2]), "+f"(c[n][3])
                    : "r"(a0), "r"(a1), "r"(a2), "r"(a3), "r"(bb[2 * n]), "r"(bb[2 * n + 1]));
            }
        }

        // Epilogue: thread holds rows {qr, qr+8}, cols n*8 + qc*2 (+1)
        const int row0 = r0 + w * 16 + qr;
#pragma unroll
        for (int n = 0; n < 8; n++) {
            int cidx = n * 4 + qc;
            if (row0 < M)
                g_Ah[(size_t)row0 * 32 + cidx] = __floats2half2_rn(c[n][0], c[n][1]);
            if (row0 + 8 < M)
                g_Ah[(size_t)(row0 + 8) * 32 + cidx] = __floats2half2_rn(c[n][2], c[n][3]);
        }
    }
}

// ---------------- Gather (+ optional fused head) ----------------

template <bool HEAD>
__global__ __launch_bounds__(256) void gather_kernel(
    const float* __restrict__ b, int relu,
    const float* __restrict__ Wl, const float* __restrict__ bl,
    float* __restrict__ out)
{
    __shared__ float Wls[HEAD ? 64 * OUTD : 1];
    __shared__ float bls[HEAD ? OUTD : 1];
    __shared__ float rowS[HEAD ? 8 : 1][64];

    const int tid = threadIdx.x;
    if (HEAD) {
        for (int i = tid; i < 64 * OUTD; i += 256) Wls[i] = Wl[i];
        if (tid < OUTD) bls[tid] = bl[tid];
        __syncthreads();
    }

    int node = (blockIdx.x * blockDim.x + tid) >> 5;
    int lane = tid & 31;
    if (node >= NN) return;

    int end = g_bsum[node >> 8] + g_off[node];   // off is inclusive end after fill
    int j0 = end - g_deg[node];

    float a0 = 0.f, a1 = 0.f;

    for (int base = j0; base < end; base += 32) {
        int rem = end - base;
        int2 meta = make_int2(0, 0);             // norm bits 0 => 0.0f padding
        if (lane < rem) meta = __ldg(&g_csr[base + lane]);
        int cnt = rem < 32 ? rem : 32;
        int nGrp = (cnt + 7) >> 3;
        for (int g = 0; g < nGrp; g++) {
            int i = g * 8;
            float2 v[8];
            float nrm[8];
#pragma unroll
            for (int u = 0; u < 8; u++) {
                int s = __shfl_sync(0xffffffffu, meta.x, i + u);
                nrm[u] = __int_as_float(__shfl_sync(0xffffffffu, meta.y, i + u));
                v[u] = __half22float2(g_Ah[(size_t)s * 32 + lane]);
            }
#pragma unroll
            for (int u = 0; u < 8; u++) {
                a0 = fmaf(v[u].x, nrm[u], a0);
                a1 = fmaf(v[u].y, nrm[u], a1);
            }
        }
    }

    float di = g_dinv[node];
    float self = di * di;
    float2 vs = __half22float2(g_Ah[(size_t)node * 32 + lane]);
    a0 = fmaf(vs.x, self, a0) + b[2 * lane];
    a1 = fmaf(vs.y, self, a1) + b[2 * lane + 1];

    if (!HEAD) {
        if (relu) { a0 = fmaxf(a0, 0.f); a1 = fmaxf(a1, 0.f); }
        *(float2*)&g_B[(size_t)node * 64 + 2 * lane] = make_float2(a0, a1);
        return;
    }

    // Fused head: logits = emb @ Wl + bl; out = log_softmax(logits).
    const int w = tid >> 5;
    rowS[w][2 * lane] = a0;
    rowS[w][2 * lane + 1] = a1;
    __syncwarp();

    float acc0 = bls[lane];
    float acc1 = (lane < 8) ? bls[32 + lane] : 0.f;
#pragma unroll
    for (int k = 0; k < 64; k++) {
        float ek = rowS[w][k];
        acc0 = fmaf(ek, Wls[k * OUTD + lane], acc0);
        if (lane < 8) acc1 = fmaf(ek, Wls[k * OUTD + 32 + lane], acc1);
    }

    float m = acc0;
    if (lane < 8) m = fmaxf(m, acc1);
#pragma unroll
    for (int off = 16; off; off >>= 1) m = fmaxf(m, __shfl_xor_sync(0xffffffffu, m, off));
    float sum = expf(acc0 - m) + ((lane < 8) ? expf(acc1 - m) : 0.f);
#pragma unroll
    for (int off = 16; off; off >>= 1) sum += __shfl_xor_sync(0xffffffffu, sum, off);
    float lse = m + logf(sum);

    out[(size_t)node * OUTD + lane] = acc0 - lse;
    if (lane < 8) out[(size_t)node * OUTD + 32 + lane] = acc1 - lse;
}

// ---------------- Launch ----------------

extern "C" void kernel_launch(void* const* d_in, const int* in_sizes, int n_in,
                              void* d_out, int out_size)
{
    const float* x  = (const float*)d_in[0];
    const void*  ei = d_in[1];
    const float* W1 = (const float*)d_in[2];
    const float* b1 = (const float*)d_in[3];
    const float* W2 = (const float*)d_in[4];
    const float* b2 = (const float*)d_in[5];
    const float* Wl = (const float*)d_in[6];
    const float* bl = (const float*)d_in[7];
    float* out = (float*)d_out;

    const int M = NN;
    const int NBLK = (NN + 255) / 256;
    const int EBLK = (NE + 255) / 256;
    const int GBLK = (M + 255) / 256;   // 4 row-tiles of 64 per block

    // CSR build; gemm1 placed at launch index 3 (profiled).
    zero_detect_kernel<<<NBLK, 256>>>((const int*)ei);
    deg_kernel<<<EBLK, 256>>>(ei);
    scan1<<<NB, 256>>>();
    gemm_tc<IN_DIM, false><<<GBLK, 128>>>(x, W1, M);
    scan2<<<1, 512>>>();
    fill_kernel<<<EBLK, 256>>>(ei);

    // Layer 1 aggregate
    gather_kernel<false><<<(M * 32 + 255) / 256, 256>>>(b1, 1, nullptr, nullptr, nullptr);

    // Layer 2 + fused head
    gemm_tc<HID, true><<<GBLK, 128>>>(nullptr, W2, M);
    gather_kernel<true><<<(M * 32 + 255) / 256, 256>>>(b2, 0, Wl, bl, out);
}